// round 1
// baseline (speedup 1.0000x reference)
#include <cuda_runtime.h>
#include <math.h>

#define N_NODES 40000
#define E_EDGES 640000
#define IN_DIM  256
#define H_DIM   128
#define C_DIM   64
#define L_LAYERS 4
#define ALPHA   0.5f

// ---------------- device scratch (no allocations allowed) ----------------
__device__ float g_h[N_NODES * H_DIM];     // current node features
__device__ float g_f0[N_NODES * H_DIM];    // ALPHA * h0 (initial residual)
__device__ float g_feat[N_NODES * H_DIM];  // (1-ALPHA)*normalized aggregation
__device__ float g_agg[N_NODES * H_DIM];   // raw scatter accumulator
__device__ float g_deg_out[N_NODES];
__device__ float g_deg_in[N_NODES];
__device__ float g_norm_s[N_NODES];
__device__ float g_norm_d[N_NODES];

// ---------------- init: zero agg + degree counters ----------------
__global__ void init_kernel() {
    int i = blockIdx.x * blockDim.x + threadIdx.x;
    if (i < N_NODES * H_DIM) g_agg[i] = 0.f;
    if (i < N_NODES) { g_deg_out[i] = 0.f; g_deg_in[i] = 0.f; }
}

__global__ void deg_kernel(const int* __restrict__ src, const int* __restrict__ dst) {
    int e = blockIdx.x * blockDim.x + threadIdx.x;
    if (e < E_EDGES) {
        atomicAdd(&g_deg_out[src[e]], 1.f);
        atomicAdd(&g_deg_in[dst[e]], 1.f);
    }
}

__global__ void norm_kernel() {
    int i = blockIdx.x * blockDim.x + threadIdx.x;
    if (i < N_NODES) {
        g_norm_s[i] = rsqrtf(fmaxf(g_deg_out[i], 1.f));
        g_norm_d[i] = rsqrtf(fmaxf(g_deg_in[i], 1.f));
    }
}

// ---------------- SpMM scatter: one warp per edge, 128 floats ----------------
__global__ void scatter_kernel(const int* __restrict__ src, const int* __restrict__ dst) {
    int gtid = blockIdx.x * blockDim.x + threadIdx.x;
    int e = gtid >> 5;
    int lane = gtid & 31;
    if (e >= E_EDGES) return;
    int s = src[e];
    int d = dst[e];
    float ns = g_norm_s[s];
    float4 v = ((const float4*)(g_h + (size_t)s * H_DIM))[lane];
    float* ad = g_agg + (size_t)d * H_DIM + lane * 4;
    atomicAdd(ad + 0, v.x * ns);
    atomicAdd(ad + 1, v.y * ns);
    atomicAdd(ad + 2, v.z * ns);
    atomicAdd(ad + 3, v.w * ns);
}

// ---------------- finalize: feat = (1-ALPHA)*norm_d*agg ; re-zero agg ----------------
__global__ void finalize_kernel() {
    int i = blockIdx.x * blockDim.x + threadIdx.x;   // over float4 elements
    const int total4 = N_NODES * H_DIM / 4;
    if (i >= total4) return;
    int row = i / (H_DIM / 4);
    float s = (1.f - ALPHA) * g_norm_d[row];
    float4 a = ((float4*)g_agg)[i];
    float4 f;
    f.x = a.x * s; f.y = a.y * s; f.z = a.z * s; f.w = a.w * s;
    ((float4*)g_feat)[i] = f;
    ((float4*)g_agg)[i] = make_float4(0.f, 0.f, 0.f, 0.f);
}

// ---------------- fused tiled GEMM ----------------
// MODE 0: h = relu(x @ fc1_w + b); f0 = ALPHA*h           (A1 = x param)
// MODE 1: acc = feat@W1 + f0@W2 (two K passes);
//         h = relu((1-beta)*(feat+f0) + beta*acc + bgc + h)   (in place)
// MODE 2: Cout = h @ fc2_w + b
constexpr int BM = 64, BN = 64, BK = 16;

template <int MODE>
__global__ void gemm_kernel(const float* __restrict__ A1,
                            const float* __restrict__ B1,
                            const float* __restrict__ B2,
                            const float* __restrict__ bias,
                            float* __restrict__ Cout,
                            int Ncols, int K, float beta) {
    __shared__ float As[BM][BK + 1];
    __shared__ float Bs[BK][BN + 1];

    int tid = threadIdx.x;
    int tx = tid & 15;          // 0..15 -> column group
    int ty = tid >> 4;          // 0..15 -> row group
    int rowBase = blockIdx.y * BM;
    int colBase = blockIdx.x * BN;

    float acc[4][4] = {};

    const int nPass = (MODE == 1) ? 2 : 1;
    for (int p = 0; p < nPass; ++p) {
        const float* A;
        if (MODE == 0)      A = A1;
        else if (MODE == 1) A = p ? (const float*)g_f0 : (const float*)g_feat;
        else                A = (const float*)g_h;
        const float* B = (MODE == 1 && p) ? B2 : B1;

        for (int kb = 0; kb < K; kb += BK) {
            {   // load A tile 64x16, 4 contiguous floats / thread
                int r = tid >> 2;
                int c = (tid & 3) * 4;
                float4 v = *(const float4*)(A + (size_t)(rowBase + r) * K + kb + c);
                As[r][c + 0] = v.x; As[r][c + 1] = v.y;
                As[r][c + 2] = v.z; As[r][c + 3] = v.w;
            }
            {   // load B tile 16x64
                int r = tid >> 4;
                int c = (tid & 15) * 4;
                float4 v = *(const float4*)(B + (size_t)(kb + r) * Ncols + colBase + c);
                Bs[r][c + 0] = v.x; Bs[r][c + 1] = v.y;
                Bs[r][c + 2] = v.z; Bs[r][c + 3] = v.w;
            }
            __syncthreads();
            #pragma unroll
            for (int kk = 0; kk < BK; ++kk) {
                float a[4], b[4];
                #pragma unroll
                for (int i = 0; i < 4; ++i) a[i] = As[ty * 4 + i][kk];
                #pragma unroll
                for (int j = 0; j < 4; ++j) b[j] = Bs[kk][tx * 4 + j];
                #pragma unroll
                for (int i = 0; i < 4; ++i)
                    #pragma unroll
                    for (int j = 0; j < 4; ++j)
                        acc[i][j] += a[i] * b[j];
            }
            __syncthreads();
        }
    }

    // epilogue
    #pragma unroll
    for (int i = 0; i < 4; ++i) {
        int r = rowBase + ty * 4 + i;
        #pragma unroll
        for (int j = 0; j < 4; ++j) {
            int c = colBase + tx * 4 + j;
            float v = acc[i][j];
            if (MODE == 0) {
                int idx = r * H_DIM + c;
                v += bias[c];
                v = fmaxf(v, 0.f);
                g_h[idx] = v;
                g_f0[idx] = ALPHA * v;
            } else if (MODE == 1) {
                int idx = r * H_DIM + c;
                float rst = (1.f - beta) * (g_feat[idx] + g_f0[idx]) + beta * v + bias[c];
                g_h[idx] = fmaxf(rst + g_h[idx], 0.f);
            } else {
                Cout[(size_t)r * Ncols + c] = v + bias[c];
            }
        }
    }
}

// ---------------- launch ----------------
extern "C" void kernel_launch(void* const* d_in, const int* in_sizes, int n_in,
                              void* d_out, int out_size) {
    const float* x     = (const float*)d_in[0];
    const float* fc1_w = (const float*)d_in[1];
    const float* fc1_b = (const float*)d_in[2];
    const float* W1    = (const float*)d_in[3];   // [L,H,H]
    const float* W2    = (const float*)d_in[4];   // [L,H,H]
    const float* bgc   = (const float*)d_in[5];   // [L,H]
    const float* fc2_w = (const float*)d_in[6];
    const float* fc2_b = (const float*)d_in[7];
    const int*   src   = (const int*)d_in[8];
    const int*   dst   = (const int*)d_in[9];
    float*       out   = (float*)d_out;

    const int TPB = 256;

    init_kernel<<<(N_NODES * H_DIM + TPB - 1) / TPB, TPB>>>();
    deg_kernel<<<(E_EDGES + TPB - 1) / TPB, TPB>>>(src, dst);
    norm_kernel<<<(N_NODES + TPB - 1) / TPB, TPB>>>();

    // fc1: M=40000, K=256, Ncols=128
    gemm_kernel<0><<<dim3(H_DIM / BN, N_NODES / BM), TPB>>>(
        x, fc1_w, nullptr, fc1_b, nullptr, H_DIM, IN_DIM, 0.f);

    const int scatterBlocks = (E_EDGES * 32 + TPB - 1) / TPB;
    const int finBlocks = (N_NODES * H_DIM / 4 + TPB - 1) / TPB;

    for (int l = 0; l < L_LAYERS; ++l) {
        float beta = logf(1.0f / (float)(l + 1) + 1.0f);
        scatter_kernel<<<scatterBlocks, TPB>>>(src, dst);
        finalize_kernel<<<finBlocks, TPB>>>();
        gemm_kernel<1><<<dim3(H_DIM / BN, N_NODES / BM), TPB>>>(
            nullptr, W1 + (size_t)l * H_DIM * H_DIM, W2 + (size_t)l * H_DIM * H_DIM,
            bgc + (size_t)l * H_DIM, nullptr, H_DIM, H_DIM, beta);
    }

    // fc2: M=40000, K=128, Ncols=64
    gemm_kernel<2><<<dim3(C_DIM / BN, N_NODES / BM), TPB>>>(
        nullptr, fc2_w, nullptr, fc2_b, out, C_DIM, H_DIM, 0.f);
}

// round 2
// speedup vs baseline: 1.1811x; 1.1811x over previous
#include <cuda_runtime.h>
#include <math.h>

#define N_NODES 40000
#define E_EDGES 640000
#define IN_DIM  256
#define H_DIM   128
#define C_DIM   64
#define L_LAYERS 4
#define ALPHA   0.5f
#define SCAN_B  1024
#define SCAN_NB 40   // ceil(40000/1024)

// ---------------- device scratch (no allocations allowed) ----------------
__device__ float g_h[N_NODES * H_DIM];     // current node features
__device__ float g_f0[N_NODES * H_DIM];    // ALPHA * h0 (initial residual)
__device__ float g_feat[N_NODES * H_DIM];  // (1-ALPHA)*normalized aggregation
__device__ float g_norm_s[N_NODES];
__device__ float g_norm_d[N_NODES];
__device__ int   g_cnt_in[N_NODES];
__device__ int   g_cnt_out[N_NODES];
__device__ int   g_fill[N_NODES];
__device__ int   g_rowptr[N_NODES + 1];
__device__ int   g_bsum[SCAN_NB];
__device__ int   g_boff[SCAN_NB];
__device__ int   g_csr_src[E_EDGES];
__device__ float g_csr_w[E_EDGES];

// ---------------- CSR build ----------------
__global__ void init_kernel() {
    int i = blockIdx.x * blockDim.x + threadIdx.x;
    if (i < N_NODES) { g_cnt_in[i] = 0; g_cnt_out[i] = 0; g_fill[i] = 0; }
}

__global__ void count_kernel(const int* __restrict__ src, const int* __restrict__ dst) {
    int e = blockIdx.x * blockDim.x + threadIdx.x;
    if (e < E_EDGES) {
        atomicAdd(&g_cnt_in[dst[e]], 1);
        atomicAdd(&g_cnt_out[src[e]], 1);
    }
}

__global__ void scan1_kernel() {
    __shared__ int sh[SCAN_B];
    int tid = threadIdx.x;
    int gid = blockIdx.x * SCAN_B + tid;
    int v = (gid < N_NODES) ? g_cnt_in[gid] : 0;
    sh[tid] = v;
    __syncthreads();
    for (int off = 1; off < SCAN_B; off <<= 1) {
        int t = (tid >= off) ? sh[tid - off] : 0;
        __syncthreads();
        sh[tid] += t;
        __syncthreads();
    }
    if (gid < N_NODES) g_rowptr[gid] = sh[tid] - v;   // exclusive
    if (tid == SCAN_B - 1) g_bsum[blockIdx.x] = sh[tid];
}

__global__ void scan2_kernel() {
    if (threadIdx.x == 0) {
        int s = 0;
        for (int b = 0; b < SCAN_NB; ++b) { g_boff[b] = s; s += g_bsum[b]; }
    }
}

__global__ void scan3_kernel() {
    int gid = blockIdx.x * blockDim.x + threadIdx.x;
    if (gid < N_NODES) {
        g_rowptr[gid] += g_boff[gid >> 10];
        g_norm_s[gid] = rsqrtf(fmaxf((float)g_cnt_out[gid], 1.f));
        g_norm_d[gid] = rsqrtf(fmaxf((float)g_cnt_in[gid], 1.f));
    }
    if (gid == 0) g_rowptr[N_NODES] = E_EDGES;
}

__global__ void fill_kernel(const int* __restrict__ src, const int* __restrict__ dst) {
    int e = blockIdx.x * blockDim.x + threadIdx.x;
    if (e < E_EDGES) {
        int d = dst[e];
        int s = src[e];
        int pos = g_rowptr[d] + atomicAdd(&g_fill[d], 1);
        g_csr_src[pos] = s;
        g_csr_w[pos] = g_norm_s[s];
    }
}

// ---------------- gather SpMM: one warp per dst row ----------------
__global__ void gather_kernel() {
    int gw = (blockIdx.x * blockDim.x + threadIdx.x) >> 5;
    int lane = threadIdx.x & 31;
    if (gw >= N_NODES) return;
    int beg = g_rowptr[gw];
    int end = g_rowptr[gw + 1];
    float4 acc = make_float4(0.f, 0.f, 0.f, 0.f);
    for (int base = beg; base < end; base += 32) {
        int e = base + lane;
        int s = 0; float wgt = 0.f;
        if (e < end) { s = g_csr_src[e]; wgt = g_csr_w[e]; }
        int cnt = min(32, end - base);
        for (int j = 0; j < cnt; ++j) {
            int   sj = __shfl_sync(0xffffffffu, s, j);
            float wj = __shfl_sync(0xffffffffu, wgt, j);
            float4 v = ((const float4*)(g_h + (size_t)sj * H_DIM))[lane];
            acc.x += v.x * wj; acc.y += v.y * wj;
            acc.z += v.z * wj; acc.w += v.w * wj;
        }
    }
    float sc = (1.f - ALPHA) * g_norm_d[gw];
    float4 r;
    r.x = acc.x * sc; r.y = acc.y * sc; r.z = acc.z * sc; r.w = acc.w * sc;
    ((float4*)(g_feat + (size_t)gw * H_DIM))[lane] = r;
}

// ---------------- fused tiled GEMM (k-major A tile, all LDS.128) ----------------
// MODE 0: h = relu(x @ fc1_w + b); f0 = ALPHA*h
// MODE 1: acc = feat@W1 + f0@W2; h = relu((1-beta)*(feat+f0) + beta*acc + bgc + h)
// MODE 2: Cout = h @ fc2_w + b
template <int MODE, int BN>
__global__ void gemm_kernel(const float* __restrict__ A1,
                            const float* __restrict__ B1,
                            const float* __restrict__ B2,
                            const float* __restrict__ bias,
                            float* __restrict__ Cout,
                            int Ncols, int K, float beta) {
    constexpr int BM = 64, BK = 16, TN = BN / 16;
    __shared__ float As[BK][BM + 4];   // k-major
    __shared__ float Bs[BK][BN + 4];

    int tid = threadIdx.x;
    int tx = tid & 15;          // col group (TN cols each)
    int ty = tid >> 4;          // row group (4 rows each)
    int rowBase = blockIdx.y * BM;
    int colBase = blockIdx.x * BN;

    float acc[4][TN] = {};

    const int nPass = (MODE == 1) ? 2 : 1;
    for (int p = 0; p < nPass; ++p) {
        const float* A;
        if (MODE == 0)      A = A1;
        else if (MODE == 1) A = p ? (const float*)g_f0 : (const float*)g_feat;
        else                A = (const float*)g_h;
        const float* B = (MODE == 1 && p) ? B2 : B1;

        for (int kb = 0; kb < K; kb += BK) {
            {   // A tile: 64x16, transpose into k-major smem
                int r = tid >> 2;
                int kc = (tid & 3) * 4;
                float4 v = *(const float4*)(A + (size_t)(rowBase + r) * K + kb + kc);
                As[kc + 0][r] = v.x; As[kc + 1][r] = v.y;
                As[kc + 2][r] = v.z; As[kc + 3][r] = v.w;
            }
            {   // B tile: 16xBN
                #pragma unroll
                for (int i = tid; i < BK * BN / 4; i += 256) {
                    int r = i / (BN / 4);
                    int c = (i % (BN / 4)) * 4;
                    float4 v = *(const float4*)(B + (size_t)(kb + r) * Ncols + colBase + c);
                    *(float4*)&Bs[r][c] = v;
                }
            }
            __syncthreads();
            #pragma unroll
            for (int kk = 0; kk < BK; ++kk) {
                float4 a4 = *(const float4*)&As[kk][ty * 4];
                float av[4] = {a4.x, a4.y, a4.z, a4.w};
                #pragma unroll
                for (int j0 = 0; j0 < TN; j0 += 4) {
                    float4 b4 = *(const float4*)&Bs[kk][tx * TN + j0];
                    float bv[4] = {b4.x, b4.y, b4.z, b4.w};
                    #pragma unroll
                    for (int i = 0; i < 4; ++i)
                        #pragma unroll
                        for (int j = 0; j < 4; ++j)
                            acc[i][j0 + j] += av[i] * bv[j];
                }
            }
            __syncthreads();
        }
    }

    // epilogue
    #pragma unroll
    for (int i = 0; i < 4; ++i) {
        int r = rowBase + ty * 4 + i;
        #pragma unroll
        for (int j = 0; j < TN; ++j) {
            int c = colBase + tx * TN + j;
            float v = acc[i][j];
            if (MODE == 0) {
                int idx = r * H_DIM + c;
                v += bias[c];
                v = fmaxf(v, 0.f);
                g_h[idx] = v;
                g_f0[idx] = ALPHA * v;
            } else if (MODE == 1) {
                int idx = r * H_DIM + c;
                float rst = (1.f - beta) * (g_feat[idx] + g_f0[idx]) + beta * v + bias[c];
                g_h[idx] = fmaxf(rst + g_h[idx], 0.f);
            } else {
                Cout[(size_t)r * Ncols + c] = v + bias[c];
            }
        }
    }
}

// ---------------- launch ----------------
extern "C" void kernel_launch(void* const* d_in, const int* in_sizes, int n_in,
                              void* d_out, int out_size) {
    const float* x     = (const float*)d_in[0];
    const float* fc1_w = (const float*)d_in[1];
    const float* fc1_b = (const float*)d_in[2];
    const float* W1    = (const float*)d_in[3];
    const float* W2    = (const float*)d_in[4];
    const float* bgc   = (const float*)d_in[5];
    const float* fc2_w = (const float*)d_in[6];
    const float* fc2_b = (const float*)d_in[7];
    const int*   src   = (const int*)d_in[8];
    const int*   dst   = (const int*)d_in[9];
    float*       out   = (float*)d_out;

    const int TPB = 256;
    const int nodeBlocks = (N_NODES + TPB - 1) / TPB;
    const int edgeBlocks = (E_EDGES + TPB - 1) / TPB;

    // CSR build (once per launch; deterministic re-init every call)
    init_kernel<<<nodeBlocks, TPB>>>();
    count_kernel<<<edgeBlocks, TPB>>>(src, dst);
    scan1_kernel<<<SCAN_NB, SCAN_B>>>();
    scan2_kernel<<<1, 32>>>();
    scan3_kernel<<<nodeBlocks, TPB>>>();
    fill_kernel<<<edgeBlocks, TPB>>>(src, dst);

    // fc1: M=40000, K=256, N=128
    gemm_kernel<0, 128><<<dim3(1, N_NODES / 64), TPB>>>(
        x, fc1_w, nullptr, fc1_b, nullptr, H_DIM, IN_DIM, 0.f);

    const int gatherBlocks = (N_NODES * 32 + TPB - 1) / TPB;
    for (int l = 0; l < L_LAYERS; ++l) {
        float beta = logf(1.0f / (float)(l + 1) + 1.0f);
        gather_kernel<<<gatherBlocks, TPB>>>();
        gemm_kernel<1, 128><<<dim3(1, N_NODES / 64), TPB>>>(
            nullptr, W1 + (size_t)l * H_DIM * H_DIM, W2 + (size_t)l * H_DIM * H_DIM,
            bgc + (size_t)l * H_DIM, nullptr, H_DIM, H_DIM, beta);
    }

    // fc2: M=40000, K=128, N=64
    gemm_kernel<2, 64><<<dim3(1, N_NODES / 64), TPB>>>(
        nullptr, fc2_w, nullptr, fc2_b, out, C_DIM, H_DIM, 0.f);
}

// round 4
// speedup vs baseline: 2.4374x; 2.0636x over previous
#include <cuda_runtime.h>
#include <cuda_bf16.h>
#include <mma.h>
#include <math.h>
#include <stdint.h>

using namespace nvcuda;

#define N_NODES 40000
#define N_PAD   40064          // 313 * 128
#define E_EDGES 640000
#define IN_DIM  256
#define H_DIM   128
#define C_DIM   64
#define L_LAYERS 4
#define ALPHA   0.5f
#define SCAN_B  1024
#define SCAN_NB 40

// ======================= device scratch (no allocations allowed) =======================
__device__ float g_h[N_PAD * H_DIM];                 // current features (fp32)
__device__ __nv_bfloat16 g_xh[N_PAD * IN_DIM], g_xl[N_PAD * IN_DIM];
__device__ __nv_bfloat16 g_f0h[N_PAD * H_DIM], g_f0l[N_PAD * H_DIM];
__device__ __nv_bfloat16 g_fth[N_PAD * H_DIM], g_ftl[N_PAD * H_DIM];
__device__ __nv_bfloat16 g_hh[N_PAD * H_DIM],  g_hl[N_PAD * H_DIM];
// transposed + split weights  (B operand stored [N][K], K contiguous)
__device__ __nv_bfloat16 g_w1Th[H_DIM * IN_DIM], g_w1Tl[H_DIM * IN_DIM];
__device__ __nv_bfloat16 g_WTh[L_LAYERS * 2 * H_DIM * H_DIM], g_WTl[L_LAYERS * 2 * H_DIM * H_DIM];
__device__ __nv_bfloat16 g_w2Th[C_DIM * H_DIM], g_w2Tl[C_DIM * H_DIM];
// CSR
__device__ float g_norm_s[N_NODES], g_norm_d[N_NODES];
__device__ int   g_cnt_in[N_NODES], g_cnt_out[N_NODES], g_fill[N_NODES];
__device__ int   g_rowptr[N_NODES + 1];
__device__ int   g_bsum[SCAN_NB], g_boff[SCAN_NB];
__device__ int   g_csr_src[E_EDGES];
__device__ float g_csr_w[E_EDGES];

// ======================= small kernels =======================
__global__ void pad_zero_kernel() {
    int i = blockIdx.x * blockDim.x + threadIdx.x;
    const __nv_bfloat16 z = __float2bfloat16_rn(0.f);
    if (i < (N_PAD - N_NODES) * IN_DIM) {
        g_xh[N_NODES * IN_DIM + i] = z;
        g_xl[N_NODES * IN_DIM + i] = z;
    }
    if (i < (N_PAD - N_NODES) * H_DIM) {
        int o = N_NODES * H_DIM + i;
        g_f0h[o] = z; g_f0l[o] = z;
        g_fth[o] = z; g_ftl[o] = z;
        g_hh[o]  = z; g_hl[o]  = z;
    }
}

__global__ void init_kernel() {
    int i = blockIdx.x * blockDim.x + threadIdx.x;
    if (i < N_NODES) { g_cnt_in[i] = 0; g_cnt_out[i] = 0; g_fill[i] = 0; }
}

__global__ void count_kernel(const int* __restrict__ src, const int* __restrict__ dst) {
    int e = blockIdx.x * blockDim.x + threadIdx.x;
    if (e < E_EDGES) {
        atomicAdd(&g_cnt_in[dst[e]], 1);
        atomicAdd(&g_cnt_out[src[e]], 1);
    }
}

__global__ void scan1_kernel() {
    __shared__ int sh[SCAN_B];
    int tid = threadIdx.x;
    int gid = blockIdx.x * SCAN_B + tid;
    int v = (gid < N_NODES) ? g_cnt_in[gid] : 0;
    sh[tid] = v;
    __syncthreads();
    for (int off = 1; off < SCAN_B; off <<= 1) {
        int t = (tid >= off) ? sh[tid - off] : 0;
        __syncthreads();
        sh[tid] += t;
        __syncthreads();
    }
    if (gid < N_NODES) g_rowptr[gid] = sh[tid] - v;
    if (tid == SCAN_B - 1) g_bsum[blockIdx.x] = sh[tid];
}

__global__ void scan2_kernel() {
    __shared__ int sh[64];
    int t = threadIdx.x;
    int v = (t < SCAN_NB) ? g_bsum[t] : 0;
    sh[t] = v;
    __syncthreads();
    for (int off = 1; off < 64; off <<= 1) {
        int u = (t >= off) ? sh[t - off] : 0;
        __syncthreads();
        sh[t] += u;
        __syncthreads();
    }
    if (t < SCAN_NB) g_boff[t] = sh[t] - v;   // exclusive
}

__global__ void scan3_kernel() {
    int gid = blockIdx.x * blockDim.x + threadIdx.x;
    if (gid < N_NODES) {
        g_rowptr[gid] += g_boff[gid >> 10];
        g_norm_s[gid] = rsqrtf(fmaxf((float)g_cnt_out[gid], 1.f));
        g_norm_d[gid] = rsqrtf(fmaxf((float)g_cnt_in[gid], 1.f));
    }
    if (gid == 0) g_rowptr[N_NODES] = E_EDGES;
}

__global__ void fill_kernel(const int* __restrict__ src, const int* __restrict__ dst) {
    int e = blockIdx.x * blockDim.x + threadIdx.x;
    if (e < E_EDGES) {
        int d = dst[e], s = src[e];
        int pos = g_rowptr[d] + atomicAdd(&g_fill[d], 1);
        g_csr_src[pos] = s;
        g_csr_w[pos] = g_norm_s[s];
    }
}

__global__ void convert_x_kernel(const float* __restrict__ x) {
    int i = blockIdx.x * blockDim.x + threadIdx.x;   // float4 index
    if (i >= N_NODES * IN_DIM / 4) return;
    float4 v = ((const float4*)x)[i];
    __nv_bfloat16 b0 = __float2bfloat16_rn(v.x), b1 = __float2bfloat16_rn(v.y);
    __nv_bfloat16 b2 = __float2bfloat16_rn(v.z), b3 = __float2bfloat16_rn(v.w);
    __nv_bfloat162 h01; h01.x = b0; h01.y = b1;
    __nv_bfloat162 h23; h23.x = b2; h23.y = b3;
    __nv_bfloat162 l01; l01.x = __float2bfloat16_rn(v.x - __bfloat162float(b0));
                        l01.y = __float2bfloat16_rn(v.y - __bfloat162float(b1));
    __nv_bfloat162 l23; l23.x = __float2bfloat16_rn(v.z - __bfloat162float(b2));
                        l23.y = __float2bfloat16_rn(v.w - __bfloat162float(b3));
    size_t base = (size_t)i * 4;
    *(__nv_bfloat162*)(g_xh + base)     = h01;
    *(__nv_bfloat162*)(g_xh + base + 2) = h23;
    *(__nv_bfloat162*)(g_xl + base)     = l01;
    *(__nv_bfloat162*)(g_xl + base + 2) = l23;
}

__global__ void prep_weights_kernel(const float* __restrict__ fc1_w,
                                    const float* __restrict__ W1,
                                    const float* __restrict__ W2,
                                    const float* __restrict__ fc2_w) {
    int i = blockIdx.x * blockDim.x + threadIdx.x;
    if (i < H_DIM * IN_DIM) {            // fc1^T
        int n = i / IN_DIM, k = i % IN_DIM;
        float w = fc1_w[k * H_DIM + n];
        __nv_bfloat16 h = __float2bfloat16_rn(w);
        g_w1Th[i] = h;
        g_w1Tl[i] = __float2bfloat16_rn(w - __bfloat162float(h));
    }
    if (i < L_LAYERS * 2 * H_DIM * H_DIM) {   // W1/W2 per layer, transposed
        int l = i / (2 * H_DIM * H_DIM);
        int rem = i % (2 * H_DIM * H_DIM);
        int g = rem / (H_DIM * H_DIM);
        int nk = rem % (H_DIM * H_DIM);
        int n = nk / H_DIM, k = nk % H_DIM;
        const float* src = g ? W2 : W1;
        float w = src[(size_t)l * H_DIM * H_DIM + k * H_DIM + n];
        __nv_bfloat16 h = __float2bfloat16_rn(w);
        g_WTh[i] = h;
        g_WTl[i] = __float2bfloat16_rn(w - __bfloat162float(h));
    }
    if (i < C_DIM * H_DIM) {             // fc2^T
        int n = i / H_DIM, k = i % H_DIM;
        float w = fc2_w[k * C_DIM + n];
        __nv_bfloat16 h = __float2bfloat16_rn(w);
        g_w2Th[i] = h;
        g_w2Tl[i] = __float2bfloat16_rn(w - __bfloat162float(h));
    }
}

// ---------------- gather SpMM: one warp per dst row; writes feat bf16 splits ----------------
__global__ void gather_kernel() {
    int gw = (blockIdx.x * blockDim.x + threadIdx.x) >> 5;
    int lane = threadIdx.x & 31;
    if (gw >= N_NODES) return;
    int beg = g_rowptr[gw];
    int end = g_rowptr[gw + 1];
    float4 acc = make_float4(0.f, 0.f, 0.f, 0.f);
    for (int base = beg; base < end; base += 32) {
        int e = base + lane;
        int s = 0; float wgt = 0.f;
        if (e < end) { s = g_csr_src[e]; wgt = g_csr_w[e]; }
        int cnt = min(32, end - base);
        for (int j = 0; j < cnt; ++j) {
            int   sj = __shfl_sync(0xffffffffu, s, j);
            float wj = __shfl_sync(0xffffffffu, wgt, j);
            float4 v = ((const float4*)(g_h + (size_t)sj * H_DIM))[lane];
            acc.x += v.x * wj; acc.y += v.y * wj;
            acc.z += v.z * wj; acc.w += v.w * wj;
        }
    }
    float sc = (1.f - ALPHA) * g_norm_d[gw];
    float f0 = acc.x * sc, f1 = acc.y * sc, f2 = acc.z * sc, f3 = acc.w * sc;
    __nv_bfloat16 b0 = __float2bfloat16_rn(f0), b1 = __float2bfloat16_rn(f1);
    __nv_bfloat16 b2 = __float2bfloat16_rn(f2), b3 = __float2bfloat16_rn(f3);
    size_t base = (size_t)gw * H_DIM + lane * 4;
    __nv_bfloat162 h01; h01.x = b0; h01.y = b1;
    __nv_bfloat162 h23; h23.x = b2; h23.y = b3;
    *(__nv_bfloat162*)(g_fth + base)     = h01;
    *(__nv_bfloat162*)(g_fth + base + 2) = h23;
    __nv_bfloat162 l01; l01.x = __float2bfloat16_rn(f0 - __bfloat162float(b0));
                        l01.y = __float2bfloat16_rn(f1 - __bfloat162float(b1));
    __nv_bfloat162 l23; l23.x = __float2bfloat16_rn(f2 - __bfloat162float(b2));
                        l23.y = __float2bfloat16_rn(f3 - __bfloat162float(b3));
    *(__nv_bfloat162*)(g_ftl + base)     = l01;
    *(__nv_bfloat162*)(g_ftl + base + 2) = l23;
}

// ======================= WMMA bf16-split GEMM =======================
// MODE 0: acc = x@fc1_w  -> h = relu(acc+b); f0 splits = split(ALPHA*h)
// MODE 1: acc = feat@W1 + f0@W2 -> h = relu((1-beta)(feat+f0) + beta*acc + bgc + h)
// MODE 2: acc = h@fc2_w -> out = acc + b
// 3 bf16 products per logical GEMM: Ah*Bh + Al*Bh + Ah*Bl (lo*lo dropped).
template <int MODE>
__global__ void __launch_bounds__(256) gemm_tc(const float* __restrict__ bias,
                                               float* __restrict__ Cout,
                                               float beta, int layer, int writeH) {
    constexpr int NDIM  = (MODE == 2) ? 64 : 128;
    constexpr int KFULL = (MODE == 0) ? 256 : 128;
    constexpr int NPROD = (MODE == 1) ? 6 : 3;
    constexpr int KC = 64;
    constexpr int LDA = 72, LDB = 72, LDST = 68;
    constexpr int WN = NDIM / 2;        // warp col extent
    constexpr int FN = WN / 16;         // 4 (NDIM=128) or 2 (NDIM=64)
    constexpr int HALVES = NDIM / 64;   // 2 or 1

    // union: operand tiles (2*128*72*2B = 36864) vs fp32 epilogue stage (128*68*4 = 34816)
    __shared__ __align__(16) unsigned char smem[128 * LDA * 2 + 128 * LDB * 2];
    __nv_bfloat16* sA = (__nv_bfloat16*)smem;
    __nv_bfloat16* sB = sA + 128 * LDA;
    float* stage = (float*)smem;

    const int tid = threadIdx.x;
    const int wid = tid >> 5;
    const int wr  = wid & 3;            // 0..3 : 32-row group
    const int wc  = wid >> 2;           // 0..1 : WN-col group
    const int rowBase = blockIdx.x * 128;

    wmma::fragment<wmma::accumulator, 16, 16, 16, float> acc[2][FN];
    #pragma unroll
    for (int i = 0; i < 2; ++i)
        #pragma unroll
        for (int j = 0; j < FN; ++j)
            wmma::fill_fragment(acc[i][j], 0.f);

    for (int prod = 0; prod < NPROD; ++prod) {
        const __nv_bfloat16 *Ap, *Bp;
        if (MODE == 0) {
            Ap = (prod == 1) ? g_xl : g_xh;
            Bp = (prod == 2) ? g_w1Tl : g_w1Th;
        } else if (MODE == 1) {
            int g = prod / 3, q = prod % 3;      // g=0: feat@W1, g=1: f0@W2
            Ap = g ? ((q == 1) ? g_f0l : g_f0h) : ((q == 1) ? g_ftl : g_fth);
            size_t wo = (size_t)(layer * 2 + g) * H_DIM * H_DIM;
            Bp = (q == 2) ? (g_WTl + wo) : (g_WTh + wo);
        } else {
            Ap = (prod == 1) ? g_hl : g_hh;
            Bp = (prod == 2) ? g_w2Tl : g_w2Th;
        }
        for (int kb = 0; kb < KFULL; kb += KC) {
            __syncthreads();   // protect smem from previous iteration's readers
            // A tile: 128 rows x 64 bf16
            #pragma unroll
            for (int i = tid; i < 128 * 8; i += 256) {
                int row = i >> 3, c8 = i & 7;
                *(uint4*)&sA[row * LDA + c8 * 8] =
                    *(const uint4*)(Ap + (size_t)(rowBase + row) * KFULL + kb + c8 * 8);
            }
            // B tile: NDIM rows x 64 bf16 ([n][k], K contiguous => col_major frag)
            #pragma unroll
            for (int i = tid; i < NDIM * 8; i += 256) {
                int row = i >> 3, c8 = i & 7;
                *(uint4*)&sB[row * LDB + c8 * 8] =
                    *(const uint4*)(Bp + (size_t)row * KFULL + kb + c8 * 8);
            }
            __syncthreads();
            #pragma unroll
            for (int kk = 0; kk < KC / 16; ++kk) {
                wmma::fragment<wmma::matrix_a, 16, 16, 16, __nv_bfloat16, wmma::row_major> af[2];
                wmma::fragment<wmma::matrix_b, 16, 16, 16, __nv_bfloat16, wmma::col_major> bf[FN];
                #pragma unroll
                for (int i = 0; i < 2; ++i)
                    wmma::load_matrix_sync(af[i], &sA[(wr * 32 + i * 16) * LDA + kk * 16], LDA);
                #pragma unroll
                for (int j = 0; j < FN; ++j)
                    wmma::load_matrix_sync(bf[j], &sB[(wc * WN + j * 16) * LDB + kk * 16], LDB);
                #pragma unroll
                for (int i = 0; i < 2; ++i)
                    #pragma unroll
                    for (int j = 0; j < FN; ++j)
                        wmma::mma_sync(acc[i][j], af[i], bf[j], acc[i][j]);
            }
        }
    }

    // epilogue in 64-column halves, staged through fp32 smem
    #pragma unroll
    for (int hf = 0; hf < HALVES; ++hf) {
        __syncthreads();
        #pragma unroll
        for (int i = 0; i < 2; ++i)
            #pragma unroll
            for (int j = 0; j < FN; ++j) {
                int col = wc * WN + j * 16;
                if (col >= hf * 64 && col < (hf + 1) * 64)
                    wmma::store_matrix_sync(&stage[(wr * 32 + i * 16) * LDST + (col - hf * 64)],
                                            acc[i][j], LDST, wmma::mem_row_major);
            }
        __syncthreads();
        for (int i = tid; i < 128 * 64; i += 256) {
            int row = i >> 6, c = i & 63;
            int r = rowBase + row, col = hf * 64 + c;
            if (r >= N_NODES) continue;
            float a = stage[row * LDST + c];
            if (MODE == 0) {
                float v = fmaxf(a + bias[col], 0.f);
                int idx = r * H_DIM + col;
                g_h[idx] = v;
                float f0 = ALPHA * v;
                __nv_bfloat16 h = __float2bfloat16_rn(f0);
                g_f0h[idx] = h;
                g_f0l[idx] = __float2bfloat16_rn(f0 - __bfloat162float(h));
            } else if (MODE == 1) {
                int idx = r * H_DIM + col;
                float feat = __bfloat162float(g_fth[idx]) + __bfloat162float(g_ftl[idx]);
                float f0   = __bfloat162float(g_f0h[idx]) + __bfloat162float(g_f0l[idx]);
                float rst = (1.f - beta) * (feat + f0) + beta * a + bias[col];
                float v = fmaxf(rst + g_h[idx], 0.f);
                g_h[idx] = v;
                if (writeH) {
                    __nv_bfloat16 h = __float2bfloat16_rn(v);
                    g_hh[idx] = h;
                    g_hl[idx] = __float2bfloat16_rn(v - __bfloat162float(h));
                }
            } else {
                Cout[(size_t)r * C_DIM + col] = a + bias[col];
            }
        }
    }
}

// ======================= launch =======================
extern "C" void kernel_launch(void* const* d_in, const int* in_sizes, int n_in,
                              void* d_out, int out_size) {
    const float* x     = (const float*)d_in[0];
    const float* fc1_w = (const float*)d_in[1];
    const float* fc1_b = (const float*)d_in[2];
    const float* W1    = (const float*)d_in[3];
    const float* W2    = (const float*)d_in[4];
    const float* bgc   = (const float*)d_in[5];
    const float* fc2_w = (const float*)d_in[6];
    const float* fc2_b = (const float*)d_in[7];
    const int*   src   = (const int*)d_in[8];
    const int*   dst   = (const int*)d_in[9];
    float*       out   = (float*)d_out;

    const int TPB = 256;
    const int nodeBlocks = (N_NODES + TPB - 1) / TPB;
    const int edgeBlocks = (E_EDGES + TPB - 1) / TPB;
    const int TILES = N_PAD / 128;   // 313

    pad_zero_kernel<<<((N_PAD - N_NODES) * IN_DIM + TPB - 1) / TPB, TPB>>>();

    // CSR build
    init_kernel<<<nodeBlocks, TPB>>>();
    count_kernel<<<edgeBlocks, TPB>>>(src, dst);
    scan1_kernel<<<SCAN_NB, SCAN_B>>>();
    scan2_kernel<<<1, 64>>>();
    scan3_kernel<<<nodeBlocks, TPB>>>();
    fill_kernel<<<edgeBlocks, TPB>>>(src, dst);

    // operand prep
    convert_x_kernel<<<(N_NODES * IN_DIM / 4 + TPB - 1) / TPB, TPB>>>(x);
    prep_weights_kernel<<<(L_LAYERS * 2 * H_DIM * H_DIM + TPB - 1) / TPB, TPB>>>(
        fc1_w, W1, W2, fc2_w);

    // fc1
    gemm_tc<0><<<TILES, 256>>>(fc1_b, nullptr, 0.f, 0, 0);

    const int gatherBlocks = (N_NODES * 32 + TPB - 1) / TPB;
    for (int l = 0; l < L_LAYERS; ++l) {
        float beta = logf(1.0f / (float)(l + 1) + 1.0f);
        gather_kernel<<<gatherBlocks, TPB>>>();
        gemm_tc<1><<<TILES, 256>>>(bgc + (size_t)l * H_DIM, nullptr, beta, l,
                                   (l == L_LAYERS - 1) ? 1 : 0);
    }

    // fc2
    gemm_tc<2><<<TILES, 256>>>(fc2_b, out, 0.f, 0, 0);
}